// round 1
// baseline (speedup 1.0000x reference)
#include <cuda_runtime.h>
#include <cstddef>

// Problem constants (from reference): h_sparse (N,K,B) f32, topk_idxs (N,K) i32,
// U (M, D+1, B) f32. Outputs: writes (N,D) f32 then scalar loss.
#define TOK_N 8192
#define KK    4
#define BB    16
#define MM    64
#define DD    512
#define DP1   513

// Scratch (no allocations allowed in kernel_launch)
__device__ float g_inv[MM * BB];       // 1/||U[:,:,b]|| per (expert, b)
__device__ float g_partial[TOK_N];     // per-token loss partials

// ---------------------------------------------------------------------------
// Kernel 1: column norms. inv[m,b] = rsqrt( sum_{d=0..512} U[m,d,b]^2 )
// (norm includes the padded row D, matching the reference)
// ---------------------------------------------------------------------------
__global__ void norm_kernel(const float* __restrict__ U) {
    int t = blockIdx.x * blockDim.x + threadIdx.x;
    if (t >= MM * BB) return;
    int m = t >> 4;
    int b = t & 15;
    const float* p = U + (size_t)m * DP1 * BB + b;
    float s = 0.f;
#pragma unroll 8
    for (int d = 0; d < DP1; ++d) {
        float v = p[(size_t)d * BB];
        s += v * v;
    }
    g_inv[t] = rsqrtf(s);
}

// ---------------------------------------------------------------------------
// Kernel 2: fused per-token writes + recon accumulation + per-token loss.
// One block per token, 128 threads. Each thread owns 4 d-values.
// Streaming over d: w[d] = sum_{k,b} U[e_k,d,b] * c[k,b]   (c = h * inv)
// then immediately r[k,b] += U[e_k,d,b] * w[d]  (U read exactly once).
// Epilogue: block-reduce r, scale by inv, diff vs h, square, partial sum.
// ---------------------------------------------------------------------------
__global__ void __launch_bounds__(128) token_kernel(
    const float* __restrict__ h, const int* __restrict__ idx,
    const float* __restrict__ U, float* __restrict__ out)
{
    const int n = blockIdx.x;
    const int t = threadIdx.x;

    __shared__ float c_s[KK * BB];     // h * inv  (writes coefficients)
    __shared__ float inv_s[KK * BB];   // inv for recon epilogue
    __shared__ int   e_s[KK];
    __shared__ float rbuf[128 * 65];   // padded (65) to avoid 32-way bank conflicts

    if (t < KK) e_s[t] = idx[n * KK + t];
    __syncthreads();
    if (t < KK * BB) {
        int k = t >> 4;
        float iv = g_inv[e_s[k] * BB + (t & 15)];
        inv_s[t] = iv;
        c_s[t] = h[(size_t)n * KK * BB + t] * iv;
    }
    __syncthreads();

    const float* Ub0 = U + (size_t)e_s[0] * DP1 * BB;
    const float* Ub1 = U + (size_t)e_s[1] * DP1 * BB;
    const float* Ub2 = U + (size_t)e_s[2] * DP1 * BB;
    const float* Ub3 = U + (size_t)e_s[3] * DP1 * BB;
    const float* Ub[KK] = {Ub0, Ub1, Ub2, Ub3};

    float r[KK][BB];
#pragma unroll
    for (int k = 0; k < KK; ++k)
#pragma unroll
        for (int b = 0; b < BB; ++b) r[k][b] = 0.f;

#pragma unroll
    for (int j = 0; j < DD / 128; ++j) {
        const int d = t + 128 * j;
        float4 u[KK][4];
        float w = 0.f;
#pragma unroll
        for (int k = 0; k < KK; ++k) {
            const float4* p = reinterpret_cast<const float4*>(Ub[k] + (size_t)d * BB);
            u[k][0] = p[0]; u[k][1] = p[1]; u[k][2] = p[2]; u[k][3] = p[3];
            const float* uf = reinterpret_cast<const float*>(&u[k][0]);
#pragma unroll
            for (int b = 0; b < BB; ++b) w += uf[b] * c_s[k * BB + b];
        }
        out[(size_t)n * DD + d] = w;   // coalesced: consecutive t -> consecutive d
#pragma unroll
        for (int k = 0; k < KK; ++k) {
            const float* uf = reinterpret_cast<const float*>(&u[k][0]);
#pragma unroll
            for (int b = 0; b < BB; ++b) r[k][b] += uf[b] * w;
        }
    }

    // ---- block reduction of r[4][16] over 128 threads ----
    float* rf = reinterpret_cast<float*>(r);
#pragma unroll
    for (int i = 0; i < 64; ++i) rbuf[t * 65 + i] = rf[i];
    __syncthreads();

    float dsq = 0.f;
    if (t < 64) {
        float s = 0.f;
        for (int tt = 0; tt < 128; ++tt) s += rbuf[tt * 65 + t];
        float rec = s * inv_s[t];                       // normalized recon
        float diff = rec - h[(size_t)n * KK * BB + t];
        dsq = diff * diff;
    }
    __syncthreads();
    rbuf[t] = dsq;
    __syncthreads();
#pragma unroll
    for (int off = 64; off > 0; off >>= 1) {
        if (t < off) rbuf[t] += rbuf[t + off];
        __syncthreads();
    }
    if (t == 0) g_partial[n] = rbuf[0];
}

// ---------------------------------------------------------------------------
// Kernel 3: deterministic final loss reduction (fixed tree, no atomics)
// ---------------------------------------------------------------------------
__global__ void loss_reduce(float* __restrict__ out_loss) {
    __shared__ float s[256];
    int t = threadIdx.x;
    float a = 0.f;
    for (int i = t; i < TOK_N; i += 256) a += g_partial[i];
    s[t] = a;
    __syncthreads();
#pragma unroll
    for (int off = 128; off > 0; off >>= 1) {
        if (t < off) s[t] += s[t + off];
        __syncthreads();
    }
    if (t == 0) *out_loss = s[0] * (1.0f / (float)(TOK_N * KK * BB));
}

// Zero any padding elements beyond [writes | loss]
__global__ void fill_tail(float* __restrict__ out, int start, int total) {
    int i = start + blockIdx.x * blockDim.x + threadIdx.x;
    if (i < total) out[i] = 0.f;
}

extern "C" void kernel_launch(void* const* d_in, const int* in_sizes, int n_in,
                              void* d_out, int out_size) {
    const float* h_sparse = (const float*)d_in[0];
    const int*   topk     = (const int*)d_in[1];
    const float* U        = (const float*)d_in[2];
    float* out = (float*)d_out;

    norm_kernel<<<(MM * BB + 127) / 128, 128>>>(U);
    token_kernel<<<TOK_N, 128>>>(h_sparse, topk, U, out);
    loss_reduce<<<1, 256>>>(out + (size_t)TOK_N * DD);

    int tail_start = TOK_N * DD + 1;
    if (out_size > tail_start) {
        int tail = out_size - tail_start;
        fill_tail<<<(tail + 255) / 256, 256>>>(out, tail_start, out_size);
    }
}

// round 2
// speedup vs baseline: 1.7422x; 1.7422x over previous
#include <cuda_runtime.h>
#include <cstddef>

#define TOK_N 8192
#define KK    4
#define BB    16
#define MM    64
#define DD    512
#define DP1   513
#define NPAIR (TOK_N*KK)   // 32768
#define SLAB  1024         // max pairs per expert (mean 512, sd ~22 -> 1024 is ~22 sigma)
#define NT1   8            // phase1 tiles per expert
#define NT2   8            // phase2 tiles per expert

// ---- scratch (__device__ globals: no runtime allocation allowed) ----
__device__ float g_inv[MM * BB];
__device__ int   g_cnt[MM];
__device__ int   g_list[MM * SLAB];
__device__ float g_wpart[(size_t)NPAIR * DD];   // 64 MB, L2-resident
__device__ float g_partial[MM * NT2];

// ---------------------------------------------------------------------------
// K1: column norms. inv[m,b] = rsqrt( sum_{d=0..512} U[m,d,b]^2 )
// One block per expert; contiguous float4 streaming. Thread i always lands in
// b-group (i%4) because 2052 float4 rows stride 256 (256%4==0).
// ---------------------------------------------------------------------------
__global__ void __launch_bounds__(256) norm_kernel(const float* __restrict__ U) {
    __shared__ float s[256 * 4];
    const int e = blockIdx.x, t = threadIdx.x;
    const float4* Ue = reinterpret_cast<const float4*>(U + (size_t)e * DP1 * BB);
    float a0 = 0.f, a1 = 0.f, a2 = 0.f, a3 = 0.f;
    for (int j = t; j < (DP1 * BB) / 4; j += 256) {   // 2052 float4
        float4 v = Ue[j];
        a0 += v.x * v.x; a1 += v.y * v.y; a2 += v.z * v.z; a3 += v.w * v.w;
    }
    s[t * 4 + 0] = a0; s[t * 4 + 1] = a1; s[t * 4 + 2] = a2; s[t * 4 + 3] = a3;
    __syncthreads();
    if (t < BB) {
        int g = t >> 2, c = t & 3;   // b = 4g + c, contributed by threads i==g (mod 4)
        float sum = 0.f;
        for (int i = g; i < 256; i += 4) sum += s[i * 4 + c];
        g_inv[e * BB + t] = rsqrtf(sum);
    }
}

// ---------------------------------------------------------------------------
// K2: deterministic per-expert compaction (counting sort into fixed slabs).
// Order within a slab is fixed by (p mod 256, p/256) -> deterministic output.
// ---------------------------------------------------------------------------
__global__ void __launch_bounds__(256) bucket_kernel(const int* __restrict__ topk) {
    __shared__ int s[256];
    const int e = blockIdx.x, t = threadIdx.x;
    int cnt = 0;
    for (int p = t; p < NPAIR; p += 256) cnt += (topk[p] == e);
    s[t] = cnt;
    __syncthreads();
    for (int off = 1; off < 256; off <<= 1) {   // inclusive Hillis-Steele scan
        int v = (t >= off) ? s[t - off] : 0;
        __syncthreads();
        s[t] += v;
        __syncthreads();
    }
    int pos = s[t] - cnt;   // exclusive prefix
    if (t == 255) g_cnt[e] = s[255];
    for (int p = t; p < NPAIR; p += 256)
        if (topk[p] == e) g_list[e * SLAB + pos++] = p;
}

// ---------------------------------------------------------------------------
// K3: phase 1 — per-expert partial writes. Thread t holds U rows d=4t..4t+3
// in registers (64 floats). Per pair: 64 FFMA against SMEM-broadcast coeffs.
// Wpart[pid][d] = sum_b Un[e,d,b] * h[pid,b]
// ---------------------------------------------------------------------------
__global__ void __launch_bounds__(128) phase1_kernel(
    const float* __restrict__ h, const float* __restrict__ U)
{
    const int e = blockIdx.x, tix = blockIdx.y, t = threadIdx.x;
    __shared__ float  inv_s[BB];
    __shared__ int    plist[64];
    __shared__ float4 c4s[256];   // 64 pairs x 16 coeffs
    const int cnt = g_cnt[e];
    if (t < BB) inv_s[t] = g_inv[e * BB + t];

    const float4* Ub = reinterpret_cast<const float4*>(U + (size_t)e * DP1 * BB);
    float4 u[4][4];
#pragma unroll
    for (int dd = 0; dd < 4; ++dd)
#pragma unroll
        for (int i = 0; i < 4; ++i)
            u[dd][i] = Ub[(4 * t + dd) * 4 + i];
    __syncthreads();

    const int nbatch = (cnt + 63) >> 6;
    for (int bi = tix; bi < nbatch; bi += NT1) {
        const int base = bi * 64;
        __syncthreads();
        if (t < 64) {
            int j = base + t;
            plist[t] = (j < cnt) ? g_list[e * SLAB + j] : -1;
        }
        __syncthreads();
        float* cs = reinterpret_cast<float*>(c4s);
#pragma unroll
        for (int q = t; q < 1024; q += 128) {
            int pp = q >> 4, b = q & 15;
            int pid = plist[pp];
            cs[q] = (pid >= 0) ? h[(size_t)pid * BB + b] * inv_s[b] : 0.f;
        }
        __syncthreads();
        for (int pp = 0; pp < 64; ++pp) {
            const int pid = plist[pp];
            if (pid < 0) break;
            const float4 c0 = c4s[pp * 4 + 0], c1 = c4s[pp * 4 + 1];
            const float4 c2 = c4s[pp * 4 + 2], c3 = c4s[pp * 4 + 3];
            float w[4];
#pragma unroll
            for (int dd = 0; dd < 4; ++dd) {
                float a;
                a  = u[dd][0].x * c0.x + u[dd][0].y * c0.y + u[dd][0].z * c0.z + u[dd][0].w * c0.w;
                a += u[dd][1].x * c1.x + u[dd][1].y * c1.y + u[dd][1].z * c1.z + u[dd][1].w * c1.w;
                a += u[dd][2].x * c2.x + u[dd][2].y * c2.y + u[dd][2].z * c2.z + u[dd][2].w * c2.w;
                a += u[dd][3].x * c3.x + u[dd][3].y * c3.y + u[dd][3].z * c3.z + u[dd][3].w * c3.w;
                w[dd] = a;
            }
            reinterpret_cast<float4*>(g_wpart + (size_t)pid * DD)[t] =
                make_float4(w[0], w[1], w[2], w[3]);
        }
    }
}

// ---------------------------------------------------------------------------
// K4: combine partials (fixed k order, deterministic) -> writes output.
// out[n,d] = sum_k Wpart[n*4+k][d]
// ---------------------------------------------------------------------------
__global__ void __launch_bounds__(256) combine_kernel(float* __restrict__ out) {
    const int gid = blockIdx.x * 256 + threadIdx.x;   // over N*128 float4
    if (gid >= TOK_N * (DD / 4)) return;
    const int n = gid >> 7, q = gid & 127;
    const float4* wp = reinterpret_cast<const float4*>(g_wpart + (size_t)n * KK * DD);
    float4 a = wp[q], b = wp[128 + q], c = wp[256 + q], d = wp[384 + q];
    float4 r = make_float4(a.x + b.x + c.x + d.x, a.y + b.y + c.y + d.y,
                           a.z + b.z + c.z + d.z, a.w + b.w + c.w + d.w);
    reinterpret_cast<float4*>(out)[gid] = r;
}

// ---------------------------------------------------------------------------
// K5: phase 2 — recon + loss. U staged in SMEM padded to 20-float rows
// (stride 80B -> conflict-free 8-lane phases for LDS.128). Warp per pair:
// lane l covers d = l + 32j; r[b] = sum_d Us[d][b] * w[n][d]; butterfly
// reduce; lane b finishes (rec = r*inv, diff vs h, square); per-block partial.
// ---------------------------------------------------------------------------
__global__ void __launch_bounds__(128) phase2_kernel(
    const float* __restrict__ h, const float* __restrict__ U,
    const float* __restrict__ w)
{
    __shared__ float Us[DD * 20];
    __shared__ float inv_s[BB];
    __shared__ float wacc[4];
    const int e = blockIdx.x, tix = blockIdx.y, t = threadIdx.x;
    const int lane = t & 31, wid = t >> 5;
    const int cnt = g_cnt[e];
    if (t < BB) inv_s[t] = g_inv[e * BB + t];

    const float4* Ub = reinterpret_cast<const float4*>(U + (size_t)e * DP1 * BB);
#pragma unroll
    for (int pass = 0; pass < 4; ++pass) {
        int d = pass * 128 + t;
        float4* dst = reinterpret_cast<float4*>(Us + d * 20);
#pragma unroll
        for (int i = 0; i < 4; ++i) dst[i] = Ub[d * 4 + i];
    }
    __syncthreads();

    float acc = 0.f;
    for (int j = tix * 4 + wid; j < cnt; j += NT2 * 4) {
        const int pid = g_list[e * SLAB + j];
        const int n = pid >> 2;
        const float* wr = w + (size_t)n * DD;
        float4 r0 = make_float4(0, 0, 0, 0), r1 = r0, r2 = r0, r3 = r0;
#pragma unroll
        for (int jj = 0; jj < 16; ++jj) {
            const int d = lane + 32 * jj;
            const float4* ur = reinterpret_cast<const float4*>(Us + d * 20);
            const float wv = __ldg(wr + d);
            float4 u0 = ur[0], u1 = ur[1], u2 = ur[2], u3 = ur[3];
            r0.x += u0.x * wv; r0.y += u0.y * wv; r0.z += u0.z * wv; r0.w += u0.w * wv;
            r1.x += u1.x * wv; r1.y += u1.y * wv; r1.z += u1.z * wv; r1.w += u1.w * wv;
            r2.x += u2.x * wv; r2.y += u2.y * wv; r2.z += u2.z * wv; r2.w += u2.w * wv;
            r3.x += u3.x * wv; r3.y += u3.y * wv; r3.z += u3.z * wv; r3.w += u3.w * wv;
        }
#pragma unroll
        for (int m = 16; m >= 1; m >>= 1) {
            r0.x += __shfl_xor_sync(0xffffffffu, r0.x, m);
            r0.y += __shfl_xor_sync(0xffffffffu, r0.y, m);
            r0.z += __shfl_xor_sync(0xffffffffu, r0.z, m);
            r0.w += __shfl_xor_sync(0xffffffffu, r0.w, m);
            r1.x += __shfl_xor_sync(0xffffffffu, r1.x, m);
            r1.y += __shfl_xor_sync(0xffffffffu, r1.y, m);
            r1.z += __shfl_xor_sync(0xffffffffu, r1.z, m);
            r1.w += __shfl_xor_sync(0xffffffffu, r1.w, m);
            r2.x += __shfl_xor_sync(0xffffffffu, r2.x, m);
            r2.y += __shfl_xor_sync(0xffffffffu, r2.y, m);
            r2.z += __shfl_xor_sync(0xffffffffu, r2.z, m);
            r2.w += __shfl_xor_sync(0xffffffffu, r2.w, m);
            r3.x += __shfl_xor_sync(0xffffffffu, r3.x, m);
            r3.y += __shfl_xor_sync(0xffffffffu, r3.y, m);
            r3.z += __shfl_xor_sync(0xffffffffu, r3.z, m);
            r3.w += __shfl_xor_sync(0xffffffffu, r3.w, m);
        }
        // lane b selects r[b]
        float sel = r0.x;
        sel = (lane == 1)  ? r0.y : sel; sel = (lane == 2)  ? r0.z : sel;
        sel = (lane == 3)  ? r0.w : sel; sel = (lane == 4)  ? r1.x : sel;
        sel = (lane == 5)  ? r1.y : sel; sel = (lane == 6)  ? r1.z : sel;
        sel = (lane == 7)  ? r1.w : sel; sel = (lane == 8)  ? r2.x : sel;
        sel = (lane == 9)  ? r2.y : sel; sel = (lane == 10) ? r2.z : sel;
        sel = (lane == 11) ? r2.w : sel; sel = (lane == 12) ? r3.x : sel;
        sel = (lane == 13) ? r3.y : sel; sel = (lane == 14) ? r3.z : sel;
        sel = (lane == 15) ? r3.w : sel;
        float dsq = 0.f;
        if (lane < BB) {
            float rec = sel * inv_s[lane];
            float tgt = __ldg(h + (size_t)pid * BB + lane);
            float df = rec - tgt;
            dsq = df * df;
        }
#pragma unroll
        for (int m = 8; m >= 1; m >>= 1) dsq += __shfl_xor_sync(0xffffffffu, dsq, m);
        if (lane == 0) acc += dsq;
    }
    __syncthreads();
    if (lane == 0) wacc[wid] = acc;
    __syncthreads();
    if (t == 0) g_partial[e * NT2 + tix] = wacc[0] + wacc[1] + wacc[2] + wacc[3];
}

// ---------------------------------------------------------------------------
// K6: deterministic fixed-tree loss reduction over MM*NT2 partials.
// ---------------------------------------------------------------------------
__global__ void __launch_bounds__(256) loss_kernel(float* __restrict__ out_loss) {
    __shared__ float s[256];
    const int t = threadIdx.x;
    float a = 0.f;
    for (int i = t; i < MM * NT2; i += 256) a += g_partial[i];
    s[t] = a;
    __syncthreads();
#pragma unroll
    for (int off = 128; off > 0; off >>= 1) {
        if (t < off) s[t] += s[t + off];
        __syncthreads();
    }
    if (t == 0) *out_loss = s[0] * (1.0f / (float)(TOK_N * KK * BB));
}

__global__ void fill_tail(float* __restrict__ out, int start, int total) {
    int i = start + blockIdx.x * blockDim.x + threadIdx.x;
    if (i < total) out[i] = 0.f;
}

extern "C" void kernel_launch(void* const* d_in, const int* in_sizes, int n_in,
                              void* d_out, int out_size) {
    const float* h_sparse = (const float*)d_in[0];
    const int*   topk     = (const int*)d_in[1];
    const float* U        = (const float*)d_in[2];
    float* out = (float*)d_out;

    norm_kernel<<<MM, 256>>>(U);
    bucket_kernel<<<MM, 256>>>(topk);
    phase1_kernel<<<dim3(MM, NT1), 128>>>(h_sparse, U);
    combine_kernel<<<(TOK_N * (DD / 4) + 255) / 256, 256>>>(out);
    phase2_kernel<<<dim3(MM, NT2), 128>>>(h_sparse, U, out);
    loss_kernel<<<1, 256>>>(out + (size_t)TOK_N * DD);

    int tail_start = TOK_N * DD + 1;
    if (out_size > tail_start) {
        int tail = out_size - tail_start;
        fill_tail<<<(tail + 255) / 256, 256>>>(out, tail_start, out_size);
    }
}

// round 3
// speedup vs baseline: 1.8936x; 1.0869x over previous
#include <cuda_runtime.h>
#include <cuda_fp16.h>
#include <cstddef>

#define TOK_N 8192
#define KK    4
#define BB    16
#define MM    64
#define DD    512
#define DP1   513
#define NPAIR (TOK_N*KK)   // 32768
#define SLAB  1024
#define NT1   16           // phase1 tiles per expert
#define BATCH 32           // pairs per phase1 batch
#define NT2   6            // phase2 tiles per expert (256-thr blocks)

// ---- scratch ----
__device__ float  g_inv[MM * BB];
__device__ int    g_cnt[MM];
__device__ int    g_list[MM * SLAB];
__device__ __half g_wph[(size_t)NPAIR * DD];   // 32 MB fp16 partials
__device__ float  g_partial[MM * NT2];

// ---------------------------------------------------------------------------
// K1: column norms. inv[m,b] = rsqrt( sum_{d=0..512} U[m,d,b]^2 )
// ---------------------------------------------------------------------------
__global__ void __launch_bounds__(256) norm_kernel(const float* __restrict__ U) {
    __shared__ float s[256 * 4];
    const int e = blockIdx.x, t = threadIdx.x;
    const float4* Ue = reinterpret_cast<const float4*>(U + (size_t)e * DP1 * BB);
    float a0 = 0.f, a1 = 0.f, a2 = 0.f, a3 = 0.f;
    for (int j = t; j < (DP1 * BB) / 4; j += 256) {
        float4 v = Ue[j];
        a0 += v.x * v.x; a1 += v.y * v.y; a2 += v.z * v.z; a3 += v.w * v.w;
    }
    s[t * 4 + 0] = a0; s[t * 4 + 1] = a1; s[t * 4 + 2] = a2; s[t * 4 + 3] = a3;
    __syncthreads();
    if (t < BB) {
        int g = t >> 2, c = t & 3;
        float sum = 0.f;
        for (int i = g; i < 256; i += 4) sum += s[i * 4 + c];
        g_inv[e * BB + t] = rsqrtf(sum);
    }
}

// ---------------------------------------------------------------------------
// K2: deterministic per-expert compaction (counting sort into fixed slabs).
// ---------------------------------------------------------------------------
__global__ void __launch_bounds__(256) bucket_kernel(const int* __restrict__ topk) {
    __shared__ int s[256];
    const int e = blockIdx.x, t = threadIdx.x;
    int cnt = 0;
    for (int p = t; p < NPAIR; p += 256) cnt += (topk[p] == e);
    s[t] = cnt;
    __syncthreads();
    for (int off = 1; off < 256; off <<= 1) {
        int v = (t >= off) ? s[t - off] : 0;
        __syncthreads();
        s[t] += v;
        __syncthreads();
    }
    int pos = s[t] - cnt;
    if (t == 255) g_cnt[e] = s[255];
    for (int p = t; p < NPAIR; p += 256)
        if (topk[p] == e) g_list[e * SLAB + pos++] = p;
}

// ---------------------------------------------------------------------------
// K3: phase 1 — per-expert partial writes into fp16. Thread t holds U rows
// d=4t..4t+3 in regs; per pair 64 FFMA vs smem-broadcast coeffs, then one
// 8-byte packed store. Wpart[pid][d] = sum_b Un[e,d,b] * h[pid,b]
// ---------------------------------------------------------------------------
__global__ void __launch_bounds__(128) phase1_kernel(
    const float* __restrict__ h, const float* __restrict__ U)
{
    const int e = blockIdx.x, tix = blockIdx.y, t = threadIdx.x;
    __shared__ float  inv_s[BB];
    __shared__ int    plist[BATCH];
    __shared__ float4 c4s[BATCH * 4];
    const int cnt = g_cnt[e];
    if (t < BB) inv_s[t] = g_inv[e * BB + t];

    const float4* Ub = reinterpret_cast<const float4*>(U + (size_t)e * DP1 * BB);
    float4 u[4][4];
#pragma unroll
    for (int dd = 0; dd < 4; ++dd)
#pragma unroll
        for (int i = 0; i < 4; ++i)
            u[dd][i] = Ub[(4 * t + dd) * 4 + i];
    __syncthreads();

    const int nbatch = (cnt + BATCH - 1) / BATCH;
    for (int bi = tix; bi < nbatch; bi += NT1) {
        const int base = bi * BATCH;
        __syncthreads();
        if (t < BATCH) {
            int j = base + t;
            plist[t] = (j < cnt) ? g_list[e * SLAB + j] : -1;
        }
        __syncthreads();
        float* cs = reinterpret_cast<float*>(c4s);
#pragma unroll
        for (int q = t; q < BATCH * BB; q += 128) {
            int pp = q >> 4, b = q & 15;
            int pid = plist[pp];
            cs[q] = (pid >= 0) ? h[(size_t)pid * BB + b] * inv_s[b] : 0.f;
        }
        __syncthreads();
        for (int pp = 0; pp < BATCH; ++pp) {
            const int pid = plist[pp];
            if (pid < 0) break;
            const float4 c0 = c4s[pp * 4 + 0], c1 = c4s[pp * 4 + 1];
            const float4 c2 = c4s[pp * 4 + 2], c3 = c4s[pp * 4 + 3];
            float w[4];
#pragma unroll
            for (int dd = 0; dd < 4; ++dd) {
                float a;
                a  = u[dd][0].x * c0.x + u[dd][0].y * c0.y + u[dd][0].z * c0.z + u[dd][0].w * c0.w;
                a += u[dd][1].x * c1.x + u[dd][1].y * c1.y + u[dd][1].z * c1.z + u[dd][1].w * c1.w;
                a += u[dd][2].x * c2.x + u[dd][2].y * c2.y + u[dd][2].z * c2.z + u[dd][2].w * c2.w;
                a += u[dd][3].x * c3.x + u[dd][3].y * c3.y + u[dd][3].z * c3.z + u[dd][3].w * c3.w;
                w[dd] = a;
            }
            __half2 p01 = __floats2half2_rn(w[0], w[1]);
            __half2 p23 = __floats2half2_rn(w[2], w[3]);
            uint2 pk;
            pk.x = *reinterpret_cast<unsigned*>(&p01);
            pk.y = *reinterpret_cast<unsigned*>(&p23);
            reinterpret_cast<uint2*>(g_wph + (size_t)pid * DD)[t] = pk;
        }
    }
}

// ---------------------------------------------------------------------------
// K4: combine fp16 partials (fixed k order, deterministic) -> fp32 writes.
// ---------------------------------------------------------------------------
__global__ void __launch_bounds__(256) combine_kernel(float* __restrict__ out) {
    const int gid = blockIdx.x * 256 + threadIdx.x;   // over N*128 float4 groups
    if (gid >= TOK_N * (DD / 4)) return;
    const int n = gid >> 7, q = gid & 127;
    const uint2* wp = reinterpret_cast<const uint2*>(g_wph + (size_t)n * KK * DD);
    float4 r = make_float4(0.f, 0.f, 0.f, 0.f);
#pragma unroll
    for (int k = 0; k < KK; ++k) {
        uint2 v = wp[k * 128 + q];
        float2 a = __half22float2(*reinterpret_cast<__half2*>(&v.x));
        float2 b = __half22float2(*reinterpret_cast<__half2*>(&v.y));
        r.x += a.x; r.y += a.y; r.z += b.x; r.w += b.y;
    }
    reinterpret_cast<float4*>(out)[gid] = r;
}

// ---------------------------------------------------------------------------
// K5: phase 2 — recon + loss. U staged once per block in stride-20 SMEM
// (conflict-free LDS.128 for d = lane + 32j). 8 warps share the tile; warp
// per pair; butterfly reduce; per-block loss partial.
// ---------------------------------------------------------------------------
__global__ void __launch_bounds__(256) phase2_kernel(
    const float* __restrict__ h, const float* __restrict__ U,
    const float* __restrict__ w)
{
    __shared__ float Us[DD * 20];
    __shared__ float inv_s[BB];
    __shared__ float wacc[8];
    const int e = blockIdx.x, tix = blockIdx.y, t = threadIdx.x;
    const int lane = t & 31, wid = t >> 5;
    const int cnt = g_cnt[e];
    if (t < BB) inv_s[t] = g_inv[e * BB + t];

    const float4* Ub = reinterpret_cast<const float4*>(U + (size_t)e * DP1 * BB);
#pragma unroll
    for (int pass = 0; pass < 2; ++pass) {
        int d = pass * 256 + t;
        float4* dst = reinterpret_cast<float4*>(Us + d * 20);
#pragma unroll
        for (int i = 0; i < 4; ++i) dst[i] = Ub[d * 4 + i];
    }
    __syncthreads();

    float acc = 0.f;
    for (int j = tix * 8 + wid; j < cnt; j += NT2 * 8) {
        const int pid = g_list[e * SLAB + j];
        const int n = pid >> 2;
        const float* wr = w + (size_t)n * DD;
        float4 r0 = make_float4(0, 0, 0, 0), r1 = r0, r2 = r0, r3 = r0;
#pragma unroll
        for (int jj = 0; jj < 16; ++jj) {
            const int d = lane + 32 * jj;
            const float4* ur = reinterpret_cast<const float4*>(Us + d * 20);
            const float wv = __ldg(wr + d);
            float4 u0 = ur[0], u1 = ur[1], u2 = ur[2], u3 = ur[3];
            r0.x += u0.x * wv; r0.y += u0.y * wv; r0.z += u0.z * wv; r0.w += u0.w * wv;
            r1.x += u1.x * wv; r1.y += u1.y * wv; r1.z += u1.z * wv; r1.w += u1.w * wv;
            r2.x += u2.x * wv; r2.y += u2.y * wv; r2.z += u2.z * wv; r2.w += u2.w * wv;
            r3.x += u3.x * wv; r3.y += u3.y * wv; r3.z += u3.z * wv; r3.w += u3.w * wv;
        }
#pragma unroll
        for (int m = 16; m >= 1; m >>= 1) {
            r0.x += __shfl_xor_sync(0xffffffffu, r0.x, m);
            r0.y += __shfl_xor_sync(0xffffffffu, r0.y, m);
            r0.z += __shfl_xor_sync(0xffffffffu, r0.z, m);
            r0.w += __shfl_xor_sync(0xffffffffu, r0.w, m);
            r1.x += __shfl_xor_sync(0xffffffffu, r1.x, m);
            r1.y += __shfl_xor_sync(0xffffffffu, r1.y, m);
            r1.z += __shfl_xor_sync(0xffffffffu, r1.z, m);
            r1.w += __shfl_xor_sync(0xffffffffu, r1.w, m);
            r2.x += __shfl_xor_sync(0xffffffffu, r2.x, m);
            r2.y += __shfl_xor_sync(0xffffffffu, r2.y, m);
            r2.z += __shfl_xor_sync(0xffffffffu, r2.z, m);
            r2.w += __shfl_xor_sync(0xffffffffu, r2.w, m);
            r3.x += __shfl_xor_sync(0xffffffffu, r3.x, m);
            r3.y += __shfl_xor_sync(0xffffffffu, r3.y, m);
            r3.z += __shfl_xor_sync(0xffffffffu, r3.z, m);
            r3.w += __shfl_xor_sync(0xffffffffu, r3.w, m);
        }
        float sel = r0.x;
        sel = (lane == 1)  ? r0.y : sel; sel = (lane == 2)  ? r0.z : sel;
        sel = (lane == 3)  ? r0.w : sel; sel = (lane == 4)  ? r1.x : sel;
        sel = (lane == 5)  ? r1.y : sel; sel = (lane == 6)  ? r1.z : sel;
        sel = (lane == 7)  ? r1.w : sel; sel = (lane == 8)  ? r2.x : sel;
        sel = (lane == 9)  ? r2.y : sel; sel = (lane == 10) ? r2.z : sel;
        sel = (lane == 11) ? r2.w : sel; sel = (lane == 12) ? r3.x : sel;
        sel = (lane == 13) ? r3.y : sel; sel = (lane == 14) ? r3.z : sel;
        sel = (lane == 15) ? r3.w : sel;
        float dsq = 0.f;
        if (lane < BB) {
            float rec = sel * inv_s[lane];
            float tgt = __ldg(h + (size_t)pid * BB + lane);
            float df = rec - tgt;
            dsq = df * df;
        }
#pragma unroll
        for (int m = 8; m >= 1; m >>= 1) dsq += __shfl_xor_sync(0xffffffffu, dsq, m);
        if (lane == 0) acc += dsq;
    }
    __syncthreads();
    if (lane == 0) wacc[wid] = acc;
    __syncthreads();
    if (t == 0) {
        float s = 0.f;
#pragma unroll
        for (int i = 0; i < 8; ++i) s += wacc[i];
        g_partial[e * NT2 + tix] = s;
    }
}

// ---------------------------------------------------------------------------
// K6: deterministic fixed-tree loss reduction.
// ---------------------------------------------------------------------------
__global__ void __launch_bounds__(256) loss_kernel(float* __restrict__ out_loss) {
    __shared__ float s[256];
    const int t = threadIdx.x;
    float a = 0.f;
    for (int i = t; i < MM * NT2; i += 256) a += g_partial[i];
    s[t] = a;
    __syncthreads();
#pragma unroll
    for (int off = 128; off > 0; off >>= 1) {
        if (t < off) s[t] += s[t + off];
        __syncthreads();
    }
    if (t == 0) *out_loss = s[0] * (1.0f / (float)(TOK_N * KK * BB));
}

__global__ void fill_tail(float* __restrict__ out, int start, int total) {
    int i = start + blockIdx.x * blockDim.x + threadIdx.x;
    if (i < total) out[i] = 0.f;
}

extern "C" void kernel_launch(void* const* d_in, const int* in_sizes, int n_in,
                              void* d_out, int out_size) {
    const float* h_sparse = (const float*)d_in[0];
    const int*   topk     = (const int*)d_in[1];
    const float* U        = (const float*)d_in[2];
    float* out = (float*)d_out;

    norm_kernel<<<MM, 256>>>(U);
    bucket_kernel<<<MM, 256>>>(topk);
    phase1_kernel<<<dim3(MM, NT1), 128>>>(h_sparse, U);
    combine_kernel<<<(TOK_N * (DD / 4) + 255) / 256, 256>>>(out);
    phase2_kernel<<<dim3(MM, NT2), 256>>>(h_sparse, U, out);
    loss_kernel<<<1, 256>>>(out + (size_t)TOK_N * DD);

    int tail_start = TOK_N * DD + 1;
    if (out_size > tail_start) {
        int tail = out_size - tail_start;
        fill_tail<<<(tail + 255) / 256, 256>>>(out, tail_start, out_size);
    }
}

// round 4
// speedup vs baseline: 1.9736x; 1.0422x over previous
#include <cuda_runtime.h>
#include <cuda_fp16.h>
#include <cstddef>

#define TOK_N 8192
#define KK    4
#define BB    16
#define MM    64
#define DD    512
#define DP1   513
#define NPAIR (TOK_N*KK)   // 32768
#define SLAB  1024
#define NT1   16           // phase1 tiles per expert
#define BATCH 32           // pairs per phase1 batch
#define NT2   6            // phase2 tiles per expert (256-thr blocks)
#define PPW   4            // phase2 pairs per warp per sweep

// ---- scratch ----
__device__ float  g_inv[MM * BB];
__device__ int    g_cnt[MM];
__device__ int    g_list[MM * SLAB];
__device__ __half g_wph[(size_t)NPAIR * DD];   // 32 MB fp16 partials
__device__ float  g_partial[MM * NT2];

// ---------------------------------------------------------------------------
// K1: column norms. inv[m,b] = rsqrt( sum_{d=0..512} U[m,d,b]^2 )
// ---------------------------------------------------------------------------
__global__ void __launch_bounds__(256) norm_kernel(const float* __restrict__ U) {
    __shared__ float s[256 * 4];
    const int e = blockIdx.x, t = threadIdx.x;
    const float4* Ue = reinterpret_cast<const float4*>(U + (size_t)e * DP1 * BB);
    float a0 = 0.f, a1 = 0.f, a2 = 0.f, a3 = 0.f;
    for (int j = t; j < (DP1 * BB) / 4; j += 256) {
        float4 v = Ue[j];
        a0 += v.x * v.x; a1 += v.y * v.y; a2 += v.z * v.z; a3 += v.w * v.w;
    }
    s[t * 4 + 0] = a0; s[t * 4 + 1] = a1; s[t * 4 + 2] = a2; s[t * 4 + 3] = a3;
    __syncthreads();
    if (t < BB) {
        int g = t >> 2, c = t & 3;
        float sum = 0.f;
        for (int i = g; i < 256; i += 4) sum += s[i * 4 + c];
        g_inv[e * BB + t] = rsqrtf(sum);
    }
}

// ---------------------------------------------------------------------------
// K2: deterministic per-expert compaction (counting sort into fixed slabs).
// ---------------------------------------------------------------------------
__global__ void __launch_bounds__(256) bucket_kernel(const int* __restrict__ topk) {
    __shared__ int s[256];
    const int e = blockIdx.x, t = threadIdx.x;
    int cnt = 0;
    for (int p = t; p < NPAIR; p += 256) cnt += (topk[p] == e);
    s[t] = cnt;
    __syncthreads();
    for (int off = 1; off < 256; off <<= 1) {
        int v = (t >= off) ? s[t - off] : 0;
        __syncthreads();
        s[t] += v;
        __syncthreads();
    }
    int pos = s[t] - cnt;
    if (t == 255) g_cnt[e] = s[255];
    for (int p = t; p < NPAIR; p += 256)
        if (topk[p] == e) g_list[e * SLAB + pos++] = p;
}

// ---------------------------------------------------------------------------
// K3: phase 1 — per-expert partial writes into fp16.
// ---------------------------------------------------------------------------
__global__ void __launch_bounds__(128) phase1_kernel(
    const float* __restrict__ h, const float* __restrict__ U)
{
    const int e = blockIdx.x, tix = blockIdx.y, t = threadIdx.x;
    __shared__ float  inv_s[BB];
    __shared__ int    plist[BATCH];
    __shared__ float4 c4s[BATCH * 4];
    const int cnt = g_cnt[e];
    if (t < BB) inv_s[t] = g_inv[e * BB + t];

    const float4* Ub = reinterpret_cast<const float4*>(U + (size_t)e * DP1 * BB);
    float4 u[4][4];
#pragma unroll
    for (int dd = 0; dd < 4; ++dd)
#pragma unroll
        for (int i = 0; i < 4; ++i)
            u[dd][i] = Ub[(4 * t + dd) * 4 + i];
    __syncthreads();

    const int nbatch = (cnt + BATCH - 1) / BATCH;
    for (int bi = tix; bi < nbatch; bi += NT1) {
        const int base = bi * BATCH;
        const int nv = min(BATCH, cnt - base);
        __syncthreads();
        if (t < BATCH) {
            int j = base + t;
            plist[t] = (j < cnt) ? g_list[e * SLAB + j] : -1;
        }
        __syncthreads();
        float* cs = reinterpret_cast<float*>(c4s);
#pragma unroll
        for (int q = t; q < BATCH * BB; q += 128) {
            int pp = q >> 4, b = q & 15;
            int pid = plist[pp];
            cs[q] = (pid >= 0) ? h[(size_t)pid * BB + b] * inv_s[b] : 0.f;
        }
        __syncthreads();
#pragma unroll 2
        for (int pp = 0; pp < nv; ++pp) {
            const int pid = plist[pp];
            const float4 c0 = c4s[pp * 4 + 0], c1 = c4s[pp * 4 + 1];
            const float4 c2 = c4s[pp * 4 + 2], c3 = c4s[pp * 4 + 3];
            float w[4];
#pragma unroll
            for (int dd = 0; dd < 4; ++dd) {
                float a;
                a  = u[dd][0].x * c0.x + u[dd][0].y * c0.y + u[dd][0].z * c0.z + u[dd][0].w * c0.w;
                a += u[dd][1].x * c1.x + u[dd][1].y * c1.y + u[dd][1].z * c1.z + u[dd][1].w * c1.w;
                a += u[dd][2].x * c2.x + u[dd][2].y * c2.y + u[dd][2].z * c2.z + u[dd][2].w * c2.w;
                a += u[dd][3].x * c3.x + u[dd][3].y * c3.y + u[dd][3].z * c3.z + u[dd][3].w * c3.w;
                w[dd] = a;
            }
            __half2 p01 = __floats2half2_rn(w[0], w[1]);
            __half2 p23 = __floats2half2_rn(w[2], w[3]);
            uint2 pk;
            pk.x = *reinterpret_cast<unsigned*>(&p01);
            pk.y = *reinterpret_cast<unsigned*>(&p23);
            reinterpret_cast<uint2*>(g_wph + (size_t)pid * DD)[t] = pk;
        }
    }
}

// ---------------------------------------------------------------------------
// K4: combine fp16 partials (fixed k order, deterministic) -> fp32 writes.
// ---------------------------------------------------------------------------
__global__ void __launch_bounds__(256) combine_kernel(float* __restrict__ out) {
    const int gid = blockIdx.x * 256 + threadIdx.x;
    if (gid >= TOK_N * (DD / 4)) return;
    const int n = gid >> 7, q = gid & 127;
    const uint2* wp = reinterpret_cast<const uint2*>(g_wph + (size_t)n * KK * DD);
    float4 r = make_float4(0.f, 0.f, 0.f, 0.f);
#pragma unroll
    for (int k = 0; k < KK; ++k) {
        uint2 v = wp[k * 128 + q];
        float2 a = __half22float2(*reinterpret_cast<__half2*>(&v.x));
        float2 b = __half22float2(*reinterpret_cast<__half2*>(&v.y));
        r.x += a.x; r.y += a.y; r.z += b.x; r.w += b.y;
    }
    reinterpret_cast<float4*>(out)[gid] = r;
}

// ---------------------------------------------------------------------------
// K5: phase 2 — recon + loss. U staged once per block in stride-20 SMEM
// (conflict-free LDS.128 for d = lane + 32j). Each warp processes PPW=4
// pairs per sweep so the U tile is read from smem once per 4 pairs.
// ---------------------------------------------------------------------------
__global__ void __launch_bounds__(256) phase2_kernel(
    const float* __restrict__ h, const float* __restrict__ U,
    const float* __restrict__ w)
{
    __shared__ float Us[DD * 20];
    __shared__ float inv_s[BB];
    __shared__ float wacc[8];
    const int e = blockIdx.x, tix = blockIdx.y, t = threadIdx.x;
    const int lane = t & 31, wid = t >> 5;
    const int cnt = g_cnt[e];
    if (t < BB) inv_s[t] = g_inv[e * BB + t];

    const float4* Ub = reinterpret_cast<const float4*>(U + (size_t)e * DP1 * BB);
#pragma unroll
    for (int pass = 0; pass < 2; ++pass) {
        int d = pass * 256 + t;
        float4* dst = reinterpret_cast<float4*>(Us + d * 20);
#pragma unroll
        for (int i = 0; i < 4; ++i) dst[i] = Ub[d * 4 + i];
    }
    __syncthreads();

    float acc = 0.f;
    const int ngroups = (cnt + PPW - 1) / PPW;
    for (int g = tix * 8 + wid; g < ngroups; g += NT2 * 8) {
        int pid[PPW];
        const float* wr[PPW];
#pragma unroll
        for (int p = 0; p < PPW; ++p) {
            int j = g * PPW + p;
            pid[p] = (j < cnt) ? g_list[e * SLAB + j] : -1;
            wr[p] = (pid[p] >= 0) ? (w + (size_t)(pid[p] >> 2) * DD) : w;
        }
        float4 r[PPW][4];
#pragma unroll
        for (int p = 0; p < PPW; ++p)
#pragma unroll
            for (int i = 0; i < 4; ++i) r[p][i] = make_float4(0, 0, 0, 0);

#pragma unroll
        for (int jj = 0; jj < 16; ++jj) {
            const int d = lane + 32 * jj;
            const float4* ur = reinterpret_cast<const float4*>(Us + d * 20);
            float wv[PPW];
#pragma unroll
            for (int p = 0; p < PPW; ++p)
                wv[p] = (pid[p] >= 0) ? __ldg(wr[p] + d) : 0.f;
            float4 u0 = ur[0], u1 = ur[1], u2 = ur[2], u3 = ur[3];
#pragma unroll
            for (int p = 0; p < PPW; ++p) {
                r[p][0].x += u0.x * wv[p]; r[p][0].y += u0.y * wv[p];
                r[p][0].z += u0.z * wv[p]; r[p][0].w += u0.w * wv[p];
                r[p][1].x += u1.x * wv[p]; r[p][1].y += u1.y * wv[p];
                r[p][1].z += u1.z * wv[p]; r[p][1].w += u1.w * wv[p];
                r[p][2].x += u2.x * wv[p]; r[p][2].y += u2.y * wv[p];
                r[p][2].z += u2.z * wv[p]; r[p][2].w += u2.w * wv[p];
                r[p][3].x += u3.x * wv[p]; r[p][3].y += u3.y * wv[p];
                r[p][3].z += u3.z * wv[p]; r[p][3].w += u3.w * wv[p];
            }
        }
#pragma unroll
        for (int m = 16; m >= 1; m >>= 1) {
#pragma unroll
            for (int p = 0; p < PPW; ++p) {
#pragma unroll
                for (int i = 0; i < 4; ++i) {
                    r[p][i].x += __shfl_xor_sync(0xffffffffu, r[p][i].x, m);
                    r[p][i].y += __shfl_xor_sync(0xffffffffu, r[p][i].y, m);
                    r[p][i].z += __shfl_xor_sync(0xffffffffu, r[p][i].z, m);
                    r[p][i].w += __shfl_xor_sync(0xffffffffu, r[p][i].w, m);
                }
            }
        }
#pragma unroll
        for (int p = 0; p < PPW; ++p) {
            float sel = r[p][0].x;
            sel = (lane == 1)  ? r[p][0].y : sel; sel = (lane == 2)  ? r[p][0].z : sel;
            sel = (lane == 3)  ? r[p][0].w : sel; sel = (lane == 4)  ? r[p][1].x : sel;
            sel = (lane == 5)  ? r[p][1].y : sel; sel = (lane == 6)  ? r[p][1].z : sel;
            sel = (lane == 7)  ? r[p][1].w : sel; sel = (lane == 8)  ? r[p][2].x : sel;
            sel = (lane == 9)  ? r[p][2].y : sel; sel = (lane == 10) ? r[p][2].z : sel;
            sel = (lane == 11) ? r[p][2].w : sel; sel = (lane == 12) ? r[p][3].x : sel;
            sel = (lane == 13) ? r[p][3].y : sel; sel = (lane == 14) ? r[p][3].z : sel;
            sel = (lane == 15) ? r[p][3].w : sel;
            float dsq = 0.f;
            if (lane < BB && pid[p] >= 0) {
                float rec = sel * inv_s[lane];
                float tgt = __ldg(h + (size_t)pid[p] * BB + lane);
                float df = rec - tgt;
                dsq = df * df;
            }
#pragma unroll
            for (int m = 8; m >= 1; m >>= 1) dsq += __shfl_xor_sync(0xffffffffu, dsq, m);
            if (lane == 0) acc += dsq;
        }
    }
    __syncthreads();
    if (lane == 0) wacc[wid] = acc;
    __syncthreads();
    if (t == 0) {
        float s = 0.f;
#pragma unroll
        for (int i = 0; i < 8; ++i) s += wacc[i];
        g_partial[e * NT2 + tix] = s;
    }
}

// ---------------------------------------------------------------------------
// K6: deterministic fixed-tree loss reduction.
// ---------------------------------------------------------------------------
__global__ void __launch_bounds__(256) loss_kernel(float* __restrict__ out_loss) {
    __shared__ float s[256];
    const int t = threadIdx.x;
    float a = 0.f;
    for (int i = t; i < MM * NT2; i += 256) a += g_partial[i];
    s[t] = a;
    __syncthreads();
#pragma unroll
    for (int off = 128; off > 0; off >>= 1) {
        if (t < off) s[t] += s[t + off];
        __syncthreads();
    }
    if (t == 0) *out_loss = s[0] * (1.0f / (float)(TOK_N * KK * BB));
}

__global__ void fill_tail(float* __restrict__ out, int start, int total) {
    int i = start + blockIdx.x * blockDim.x + threadIdx.x;
    if (i < total) out[i] = 0.f;
}

extern "C" void kernel_launch(void* const* d_in, const int* in_sizes, int n_in,
                              void* d_out, int out_size) {
    const float* h_sparse = (const float*)d_in[0];
    const int*   topk     = (const int*)d_in[1];
    const float* U        = (const float*)d_in[2];
    float* out = (float*)d_out;

    norm_kernel<<<MM, 256>>>(U);
    bucket_kernel<<<MM, 256>>>(topk);
    phase1_kernel<<<dim3(MM, NT1), 128>>>(h_sparse, U);
    combine_kernel<<<(TOK_N * (DD / 4) + 255) / 256, 256>>>(out);
    phase2_kernel<<<dim3(MM, NT2), 256>>>(h_sparse, U, out);
    loss_kernel<<<1, 256>>>(out + (size_t)TOK_N * DD);

    int tail_start = TOK_N * DD + 1;
    if (out_size > tail_start) {
        int tail = out_size - tail_start;
        fill_tail<<<(tail + 255) / 256, 256>>>(out, tail_start, out_size);
    }
}